// round 10
// baseline (speedup 1.0000x reference)
#include <cuda_runtime.h>

// Grid_nd_sample: bilinear interpolation gather. (R8 structure, 1024-thr CTAs)
// in_tensor: (B=16, H=128, W=128, C=256) fp32 (268 MB)
// indices:   (B, P=8192, 2) fp32
// out:       (B, P, C) fp32 (134 MB)
//
// DRAM traffic is at the compulsory floor (~334 MB); remaining lever is
// achieved-bandwidth %. 1024-thread CTAs -> each CTA emits one 32 KB
// contiguous write stream (vs 8 KB at 256 threads), 4x fewer concurrent
// write streams chip-wide -> better DRAM write page locality. Reads:
// 8 front-batched independent 16B gathers per thread (proven optimum).
// Streaming (.cs) stores keep the write-once output out of L2.

namespace {
constexpr int B = 16;
constexpr int H = 128;
constexpr int W = 128;
constexpr int C = 256;
constexpr int P = 8192;
constexpr int C4 = C / 4;                       // 64 float4 chunks per point
constexpr long NPAIR = (long)B * P / 2;         // 65536 point-pairs
constexpr long TOTAL = NPAIR * C4;              // 4,194,304 threads
}

__global__ __launch_bounds__(1024) void grid_sample_kernel(
    const float* __restrict__ in,
    const float* __restrict__ idx,
    float* __restrict__ out)
{
    long i = (long)blockIdx.x * blockDim.x + threadIdx.x;
    if (i >= TOTAL) return;

    int  c4   = (int)(i & (C4 - 1));   // 0..63
    long pair = i >> 6;                // pair id
    long bp0  = pair * 2;
    long bp1  = bp0 + 1;
    int  b    = (int)(bp0 >> 13);      // P = 8192 = 2^13; pair never spans images

    // Index loads: warp-uniform (all 32 lanes share one pair) -> broadcast
    float4 ii = __ldg((const float4*)(idx + bp0 * 2));  // {y0, x0, y1p, x1p}
    float iy0 = ii.x, ix0 = ii.y, iy1 = ii.z, ix1 = ii.w;

    // Point 0 coords/weights
    float fy0 = floorf(iy0), fx0 = floorf(ix0);
    int ay0 = (int)fy0, ax0 = (int)fx0;
    int by0 = (int)ceilf(iy0), bx0 = (int)ceilf(ix0);
    float muy0 = iy0 - fy0, mux0 = ix0 - fx0;

    // Point 1 coords/weights
    float fy1 = floorf(iy1), fx1 = floorf(ix1);
    int ay1 = (int)fy1, ax1 = (int)fx1;
    int by1 = (int)ceilf(iy1), bx1 = (int)ceilf(ix1);
    float muy1 = iy1 - fy1, mux1 = ix1 - fx1;

    const long img = (long)b * H * W * C;
    const float4* base = (const float4*)(in + img);

    // 8 independent gathers, front-batched for max MLP
    const float4* p0r00 = base + (((long)ay0 * W + ax0) * C4) + c4;
    const float4* p0r10 = base + (((long)by0 * W + ax0) * C4) + c4;
    const float4* p0r01 = base + (((long)ay0 * W + bx0) * C4) + c4;
    const float4* p0r11 = base + (((long)by0 * W + bx0) * C4) + c4;
    const float4* p1r00 = base + (((long)ay1 * W + ax1) * C4) + c4;
    const float4* p1r10 = base + (((long)by1 * W + ax1) * C4) + c4;
    const float4* p1r01 = base + (((long)ay1 * W + bx1) * C4) + c4;
    const float4* p1r11 = base + (((long)by1 * W + bx1) * C4) + c4;

    float4 a0 = __ldg(p0r00);
    float4 b0 = __ldg(p0r10);
    float4 c0 = __ldg(p0r01);
    float4 d0 = __ldg(p0r11);
    float4 a1 = __ldg(p1r00);
    float4 b1 = __ldg(p1r10);
    float4 c1 = __ldg(p1r01);
    float4 d1 = __ldg(p1r11);

    float w00a = (1.0f - muy0) * (1.0f - mux0);
    float w10a = muy0 * (1.0f - mux0);
    float w01a = (1.0f - muy0) * mux0;
    float w11a = muy0 * mux0;

    float w00b = (1.0f - muy1) * (1.0f - mux1);
    float w10b = muy1 * (1.0f - mux1);
    float w01b = (1.0f - muy1) * mux1;
    float w11b = muy1 * mux1;

    float4 o0, o1;
    o0.x = a0.x * w00a + b0.x * w10a + c0.x * w01a + d0.x * w11a;
    o0.y = a0.y * w00a + b0.y * w10a + c0.y * w01a + d0.y * w11a;
    o0.z = a0.z * w00a + b0.z * w10a + c0.z * w01a + d0.z * w11a;
    o0.w = a0.w * w00a + b0.w * w10a + c0.w * w01a + d0.w * w11a;

    o1.x = a1.x * w00b + b1.x * w10b + c1.x * w01b + d1.x * w11b;
    o1.y = a1.y * w00b + b1.y * w10b + c1.y * w01b + d1.y * w11b;
    o1.z = a1.z * w00b + b1.z * w10b + c1.z * w01b + d1.z * w11b;
    o1.w = a1.w * w00b + b1.w * w10b + c1.w * w01b + d1.w * w11b;

    __stcs(((float4*)(out + bp0 * C)) + c4, o0);
    __stcs(((float4*)(out + bp1 * C)) + c4, o1);
}

extern "C" void kernel_launch(void* const* d_in, const int* in_sizes, int n_in,
                              void* d_out, int out_size)
{
    const float* in_tensor = (const float*)d_in[0];
    const float* indices   = (const float*)d_in[1];
    float* out = (float*)d_out;

    const int threads = 1024;
    const long blocks = (TOTAL + threads - 1) / threads;  // 4096
    grid_sample_kernel<<<(unsigned)blocks, threads>>>(in_tensor, indices, out);
}

// round 11
// speedup vs baseline: 1.0727x; 1.0727x over previous
#include <cuda_runtime.h>

// Grid_nd_sample: bilinear interpolation gather. (R8-best structure, 512-thr)
// in_tensor: (B=16, H=128, W=128, C=256) fp32 (268 MB)
// indices:   (B, P=8192, 2) fp32
// out:       (B, P, C) fp32 (134 MB)
//
// Converged design: 2 points per thread, 8 front-batched independent 16B
// gathers (request count per thread is the variable that tracked every win),
// full occupancy (regs=32), streaming .cs stores to keep the write-once
// output out of L2's gather-reuse window. DRAM traffic is at the compulsory
// floor (~334 MB); HBM ~75% of spec is the random-read+stream-write mix
// ceiling. This round: 512-thread blocks (midpoint tune) + exact-divisible
// grid so the bounds guard is gone.

namespace {
constexpr int B = 16;
constexpr int H = 128;
constexpr int W = 128;
constexpr int C = 256;
constexpr int P = 8192;
constexpr int C4 = C / 4;                       // 64 float4 chunks per point
constexpr long NPAIR = (long)B * P / 2;         // 65536 point-pairs
constexpr long TOTAL = NPAIR * C4;              // 4,194,304 threads (= 8192*512)
}

__global__ __launch_bounds__(512) void grid_sample_kernel(
    const float* __restrict__ in,
    const float* __restrict__ idx,
    float* __restrict__ out)
{
    long i = (long)blockIdx.x * blockDim.x + threadIdx.x;

    int  c4   = (int)(i & (C4 - 1));   // 0..63
    long pair = i >> 6;                // pair id
    long bp0  = pair * 2;
    long bp1  = bp0 + 1;
    int  b    = (int)(bp0 >> 13);      // P = 8192 = 2^13; pair never spans images

    // Index loads: warp-uniform (all 32 lanes share one pair) -> broadcast
    float4 ii = __ldg((const float4*)(idx + bp0 * 2));  // {y0, x0, y1p, x1p}
    float iy0 = ii.x, ix0 = ii.y, iy1 = ii.z, ix1 = ii.w;

    // Point 0 coords/weights
    float fy0 = floorf(iy0), fx0 = floorf(ix0);
    int ay0 = (int)fy0, ax0 = (int)fx0;
    int by0 = (int)ceilf(iy0), bx0 = (int)ceilf(ix0);
    float muy0 = iy0 - fy0, mux0 = ix0 - fx0;

    // Point 1 coords/weights
    float fy1 = floorf(iy1), fx1 = floorf(ix1);
    int ay1 = (int)fy1, ax1 = (int)fx1;
    int by1 = (int)ceilf(iy1), bx1 = (int)ceilf(ix1);
    float muy1 = iy1 - fy1, mux1 = ix1 - fx1;

    const long img = (long)b * H * W * C;
    const float4* base = (const float4*)(in + img);

    // 8 independent gathers, front-batched for max MLP
    const float4* p0r00 = base + (((long)ay0 * W + ax0) * C4) + c4;
    const float4* p0r10 = base + (((long)by0 * W + ax0) * C4) + c4;
    const float4* p0r01 = base + (((long)ay0 * W + bx0) * C4) + c4;
    const float4* p0r11 = base + (((long)by0 * W + bx0) * C4) + c4;
    const float4* p1r00 = base + (((long)ay1 * W + ax1) * C4) + c4;
    const float4* p1r10 = base + (((long)by1 * W + ax1) * C4) + c4;
    const float4* p1r01 = base + (((long)ay1 * W + bx1) * C4) + c4;
    const float4* p1r11 = base + (((long)by1 * W + bx1) * C4) + c4;

    float4 a0 = __ldg(p0r00);
    float4 b0 = __ldg(p0r10);
    float4 c0 = __ldg(p0r01);
    float4 d0 = __ldg(p0r11);
    float4 a1 = __ldg(p1r00);
    float4 b1 = __ldg(p1r10);
    float4 c1 = __ldg(p1r01);
    float4 d1 = __ldg(p1r11);

    float w00a = (1.0f - muy0) * (1.0f - mux0);
    float w10a = muy0 * (1.0f - mux0);
    float w01a = (1.0f - muy0) * mux0;
    float w11a = muy0 * mux0;

    float w00b = (1.0f - muy1) * (1.0f - mux1);
    float w10b = muy1 * (1.0f - mux1);
    float w01b = (1.0f - muy1) * mux1;
    float w11b = muy1 * mux1;

    float4 o0, o1;
    o0.x = a0.x * w00a + b0.x * w10a + c0.x * w01a + d0.x * w11a;
    o0.y = a0.y * w00a + b0.y * w10a + c0.y * w01a + d0.y * w11a;
    o0.z = a0.z * w00a + b0.z * w10a + c0.z * w01a + d0.z * w11a;
    o0.w = a0.w * w00a + b0.w * w10a + c0.w * w01a + d0.w * w11a;

    o1.x = a1.x * w00b + b1.x * w10b + c1.x * w01b + d1.x * w11b;
    o1.y = a1.y * w00b + b1.y * w10b + c1.y * w01b + d1.y * w11b;
    o1.z = a1.z * w00b + b1.z * w10b + c1.z * w01b + d1.z * w11b;
    o1.w = a1.w * w00b + b1.w * w10b + c1.w * w01b + d1.w * w11b;

    __stcs(((float4*)(out + bp0 * C)) + c4, o0);
    __stcs(((float4*)(out + bp1 * C)) + c4, o1);
}

extern "C" void kernel_launch(void* const* d_in, const int* in_sizes, int n_in,
                              void* d_out, int out_size)
{
    const float* in_tensor = (const float*)d_in[0];
    const float* indices   = (const float*)d_in[1];
    float* out = (float*)d_out;

    const int threads = 512;
    const long blocks = TOTAL / threads;  // 8192, exact
    grid_sample_kernel<<<(unsigned)blocks, threads>>>(in_tensor, indices, out);
}

// round 13
// speedup vs baseline: 1.0767x; 1.0038x over previous
#include <cuda_runtime.h>

// Grid_nd_sample: bilinear interpolation gather. (Converged: R8 config)
// in_tensor: (B=16, H=128, W=128, C=256) fp32 (268 MB)
// indices:   (B, P=8192, 2) fp32
// out:       (B, P, C) fp32 (134 MB)
//
// Final design, mapped over 10 rounds:
//  - 2 points per thread, 8 front-batched independent 16B gathers
//    (deeper MLP regresses: reg pressure / no latency benefit;
//     shallower regresses: queue too shallow)
//  - 256-thread blocks (block sweep: 256 > 512 > 1024)
//  - streaming .cs stores (write-once output stays out of L2's reuse window)
//  - exact-divisible grid, no bounds guard
// DRAM traffic is at the compulsory floor (~334 MB); ~75% of spec HBM is the
// random-read + streaming-write mix ceiling.
// (R11 bench was an infra failure — container died twice; resubmitting
// the identical candidate for a clean measurement.)

namespace {
constexpr int B = 16;
constexpr int H = 128;
constexpr int W = 128;
constexpr int C = 256;
constexpr int P = 8192;
constexpr int C4 = C / 4;                       // 64 float4 chunks per point
constexpr long NPAIR = (long)B * P / 2;         // 65536 point-pairs
constexpr long TOTAL = NPAIR * C4;              // 4,194,304 threads (=16384*256)
}

__global__ __launch_bounds__(256) void grid_sample_kernel(
    const float* __restrict__ in,
    const float* __restrict__ idx,
    float* __restrict__ out)
{
    long i = (long)blockIdx.x * blockDim.x + threadIdx.x;

    int  c4   = (int)(i & (C4 - 1));   // 0..63
    long pair = i >> 6;                // pair id
    long bp0  = pair * 2;
    long bp1  = bp0 + 1;
    int  b    = (int)(bp0 >> 13);      // P = 8192 = 2^13; pair never spans images

    // Index loads: warp-uniform (all 32 lanes share one pair) -> broadcast
    float4 ii = __ldg((const float4*)(idx + bp0 * 2));  // {y0, x0, y1p, x1p}
    float iy0 = ii.x, ix0 = ii.y, iy1 = ii.z, ix1 = ii.w;

    // Point 0 coords/weights
    float fy0 = floorf(iy0), fx0 = floorf(ix0);
    int ay0 = (int)fy0, ax0 = (int)fx0;
    int by0 = (int)ceilf(iy0), bx0 = (int)ceilf(ix0);
    float muy0 = iy0 - fy0, mux0 = ix0 - fx0;

    // Point 1 coords/weights
    float fy1 = floorf(iy1), fx1 = floorf(ix1);
    int ay1 = (int)fy1, ax1 = (int)fx1;
    int by1 = (int)ceilf(iy1), bx1 = (int)ceilf(ix1);
    float muy1 = iy1 - fy1, mux1 = ix1 - fx1;

    const long img = (long)b * H * W * C;
    const float4* base = (const float4*)(in + img);

    // 8 independent gathers, front-batched for max MLP
    const float4* p0r00 = base + (((long)ay0 * W + ax0) * C4) + c4;
    const float4* p0r10 = base + (((long)by0 * W + ax0) * C4) + c4;
    const float4* p0r01 = base + (((long)ay0 * W + bx0) * C4) + c4;
    const float4* p0r11 = base + (((long)by0 * W + bx0) * C4) + c4;
    const float4* p1r00 = base + (((long)ay1 * W + ax1) * C4) + c4;
    const float4* p1r10 = base + (((long)by1 * W + ax1) * C4) + c4;
    const float4* p1r01 = base + (((long)ay1 * W + bx1) * C4) + c4;
    const float4* p1r11 = base + (((long)by1 * W + bx1) * C4) + c4;

    float4 a0 = __ldg(p0r00);
    float4 b0 = __ldg(p0r10);
    float4 c0 = __ldg(p0r01);
    float4 d0 = __ldg(p0r11);
    float4 a1 = __ldg(p1r00);
    float4 b1 = __ldg(p1r10);
    float4 c1 = __ldg(p1r01);
    float4 d1 = __ldg(p1r11);

    float w00a = (1.0f - muy0) * (1.0f - mux0);
    float w10a = muy0 * (1.0f - mux0);
    float w01a = (1.0f - muy0) * mux0;
    float w11a = muy0 * mux0;

    float w00b = (1.0f - muy1) * (1.0f - mux1);
    float w10b = muy1 * (1.0f - mux1);
    float w01b = (1.0f - muy1) * mux1;
    float w11b = muy1 * mux1;

    float4 o0, o1;
    o0.x = a0.x * w00a + b0.x * w10a + c0.x * w01a + d0.x * w11a;
    o0.y = a0.y * w00a + b0.y * w10a + c0.y * w01a + d0.y * w11a;
    o0.z = a0.z * w00a + b0.z * w10a + c0.z * w01a + d0.z * w11a;
    o0.w = a0.w * w00a + b0.w * w10a + c0.w * w01a + d0.w * w11a;

    o1.x = a1.x * w00b + b1.x * w10b + c1.x * w01b + d1.x * w11b;
    o1.y = a1.y * w00b + b1.y * w10b + c1.y * w01b + d1.y * w11b;
    o1.z = a1.z * w00b + b1.z * w10b + c1.z * w01b + d1.z * w11b;
    o1.w = a1.w * w00b + b1.w * w10b + c1.w * w01b + d1.w * w11b;

    __stcs(((float4*)(out + bp0 * C)) + c4, o0);
    __stcs(((float4*)(out + bp1 * C)) + c4, o1);
}

extern "C" void kernel_launch(void* const* d_in, const int* in_sizes, int n_in,
                              void* d_out, int out_size)
{
    const float* in_tensor = (const float*)d_in[0];
    const float* indices   = (const float*)d_in[1];
    float* out = (float*)d_out;

    const int threads = 256;
    const long blocks = TOTAL / threads;  // 16384, exact
    grid_sample_kernel<<<(unsigned)blocks, threads>>>(in_tensor, indices, out);
}